// round 4
// baseline (speedup 1.0000x reference)
#include <cuda_runtime.h>
#include <cuda_bf16.h>
#include <cstdint>
#include <math.h>

#define NB 8
#define NN 2048
#define DD 128
#define ROWS_TOT (NB * NN)

__device__ float g_buf[ROWS_TOT * DD];
__device__ __nv_bfloat16 g_hhi[ROWS_TOT * DD];
__device__ __nv_bfloat16 g_hlo[ROWS_TOT * DD];
__device__ float g_rn[ROWS_TOT];

// ---------------------------------------------------------------------------
__device__ __forceinline__ uint32_t smem_u32(const void* p) {
    uint32_t a;
    asm("{ .reg .u64 t; cvta.to.shared.u64 t, %1; cvt.u32.u64 %0, t; }" : "=r"(a) : "l"(p));
    return a;
}
__device__ __forceinline__ void mma_bf16(float* d, const uint32_t* a, const uint32_t* b) {
    asm volatile(
        "mma.sync.aligned.m16n8k16.row.col.f32.bf16.bf16.f32 "
        "{%0,%1,%2,%3}, {%4,%5,%6,%7}, {%8,%9}, {%0,%1,%2,%3};"
        : "+f"(d[0]), "+f"(d[1]), "+f"(d[2]), "+f"(d[3])
        : "r"(a[0]), "r"(a[1]), "r"(a[2]), "r"(a[3]), "r"(b[0]), "r"(b[1]));
}
__device__ __forceinline__ void ldsm4(uint32_t* r, uint32_t addr) {
    asm volatile("ldmatrix.sync.aligned.m8n8.x4.shared.b16 {%0,%1,%2,%3}, [%4];"
                 : "=r"(r[0]), "=r"(r[1]), "=r"(r[2]), "=r"(r[3]) : "r"(addr));
}
__device__ __forceinline__ void ldsm4t(uint32_t* r, uint32_t addr) {
    asm volatile("ldmatrix.sync.aligned.m8n8.x4.trans.shared.b16 {%0,%1,%2,%3}, [%4];"
                 : "=r"(r[0]), "=r"(r[1]), "=r"(r[2]), "=r"(r[3]) : "r"(addr));
}
__device__ __forceinline__ uint32_t packbf(float a, float b) {
    const uint16_t la = __bfloat16_as_ushort(__float2bfloat16(a));
    const uint16_t lb = __bfloat16_as_ushort(__float2bfloat16(b));
    return ((uint32_t)lb << 16) | la;
}
__device__ __forceinline__ void split2(float v0, float v1, uint32_t& hi, uint32_t& lo) {
    const __nv_bfloat16 h0 = __float2bfloat16(v0);
    const __nv_bfloat16 h1 = __float2bfloat16(v1);
    const float r0 = v0 - __bfloat162float(h0);
    const float r1 = v1 - __bfloat162float(h1);
    hi = ((uint32_t)__bfloat16_as_ushort(h1) << 16) | __bfloat16_as_ushort(h0);
    lo = packbf(r0, r1);
}
#define CP_ASYNC16(dst, src) \
    asm volatile("cp.async.cg.shared.global [%0], [%1], 16;" :: "r"(dst), "l"(src))
#define CP_COMMIT() asm volatile("cp.async.commit_group;" ::: "memory")
#define CP_WAIT(n)  asm volatile("cp.async.wait_group %0;" :: "n"(n) : "memory")

// ---------------------------------------------------------------------------
// Linear + bias + split + reciprocal norm (unchanged, proven)
// ---------------------------------------------------------------------------
#define SMEM_LIN ((64 * 132 + 128 * 132) * 4)

__global__ __launch_bounds__(256, 2) void linear_norm_kernel(
    const float* __restrict__ in, const float* __restrict__ W, const float* __restrict__ bias,
    __nv_bfloat16* __restrict__ hhi, __nv_bfloat16* __restrict__ hlo, float* __restrict__ rn)
{
    extern __shared__ float sm[];
    float* sx = sm;
    float* sw = sm + 64 * 132;

    const int t = threadIdx.x;
    const int rowbase = blockIdx.x * 64;
    const int f4 = (t & 31) * 4;
    const int r0 = t >> 5;

    #pragma unroll
    for (int r = r0; r < 64; r += 8)
        *(float4*)&sx[r * 132 + f4] = *(const float4*)&in[(size_t)(rowbase + r) * DD + f4];
    #pragma unroll
    for (int r = r0; r < 128; r += 8)
        *(float4*)&sw[r * 132 + f4] = *(const float4*)&W[(size_t)r * DD + f4];
    __syncthreads();

    const int tx = t & 15;
    const int ty = t >> 4;

    float acc[4][8];
    #pragma unroll
    for (int i = 0; i < 4; i++)
        #pragma unroll
        for (int j = 0; j < 8; j++) acc[i][j] = 0.0f;

    #pragma unroll 4
    for (int k = 0; k < DD; k++) {
        float a[4], w[8];
        #pragma unroll
        for (int i = 0; i < 4; i++) a[i] = sx[(ty * 4 + i) * 132 + k];
        #pragma unroll
        for (int j = 0; j < 8; j++) w[j] = sw[k * 132 + tx + 16 * j];
        #pragma unroll
        for (int i = 0; i < 4; i++)
            #pragma unroll
            for (int j = 0; j < 8; j++)
                acc[i][j] = fmaf(a[i], w[j], acc[i][j]);
    }

    float bv[8];
    #pragma unroll
    for (int j = 0; j < 8; j++) bv[j] = bias[tx + 16 * j];

    #pragma unroll
    for (int i = 0; i < 4; i++) {
        float ss = 0.0f;
        #pragma unroll
        for (int j = 0; j < 8; j++) {
            acc[i][j] += bv[j];
            ss = fmaf(acc[i][j], acc[i][j], ss);
        }
        #pragma unroll
        for (int off = 8; off > 0; off >>= 1)
            ss += __shfl_xor_sync(0xffffffffu, ss, off, 16);
        if (tx == 0)
            rn[rowbase + ty * 4 + i] = 1.0f / fmaxf(sqrtf(ss), 1e-12f);
    }

    #pragma unroll
    for (int i = 0; i < 4; i++)
        #pragma unroll
        for (int j = 0; j < 8; j++) {
            const float v = acc[i][j];
            const __nv_bfloat16 h = __float2bfloat16(v);
            const __nv_bfloat16 l = __float2bfloat16(v - __bfloat162float(h));
            const size_t idx = (size_t)(rowbase + ty * 4 + i) * DD + tx + 16 * j;
            hhi[idx] = h;
            hlo[idx] = l;
        }
}

// ---------------------------------------------------------------------------
// Fused flash aggregation. 128 threads = 4 warps, 64 p-rows/CTA, 256 CTAs
// (2 CTAs/SM). Double-buffered cp.async Hq staging.
// ---------------------------------------------------------------------------
#define QT 64
#define HQS 136                       // bf16 elems per smem row (272 B)
#define TILE_B (QT * HQS * 2)         // bytes per (hi or lo) tile = 17408
#define SMEM_FUSED (4 * TILE_B)       // 2 stages x (hi+lo)

__global__ __launch_bounds__(128, 2) void fused_mma_kernel(
    const __nv_bfloat16* __restrict__ hhi, const __nv_bfloat16* __restrict__ hlo,
    const float* __restrict__ rn, const float* __restrict__ ew,
    float* __restrict__ out, int do_relu)
{
    extern __shared__ char smem[];
    // layout: [stage0 hi][stage0 lo][stage1 hi][stage1 lo]
    const uint32_t sbase = smem_u32(smem);

    const int t = threadIdx.x;
    const int w = t >> 5;
    const int lane = t & 31;
    const int quad = lane & 3;
    const int gr = lane >> 2;
    const int b = blockIdx.y;
    const int pbase = blockIdx.x * 64;

    const __nv_bfloat16* hhB = hhi + (size_t)b * NN * DD;
    const __nv_bfloat16* hlB = hlo + (size_t)b * NN * DD;
    const float* rnB = rn + (size_t)b * NN;
    const float* ewB = ew + (size_t)b * NN * NN;

    const int prow0 = pbase + w * 16 + gr;
    const int prow1 = prow0 + 8;
    const int ac = quad * 2;

    // ---- A fragments (Hp hi/lo) resident in registers ----
    uint32_t Ahi[8][4], Alo[8][4];
    #pragma unroll
    for (int kc = 0; kc < 8; kc++) {
        Ahi[kc][0] = *(const uint32_t*)&hhB[(size_t)prow0 * DD + kc * 16 + ac];
        Ahi[kc][1] = *(const uint32_t*)&hhB[(size_t)prow1 * DD + kc * 16 + ac];
        Ahi[kc][2] = *(const uint32_t*)&hhB[(size_t)prow0 * DD + kc * 16 + 8 + ac];
        Ahi[kc][3] = *(const uint32_t*)&hhB[(size_t)prow1 * DD + kc * 16 + 8 + ac];
        Alo[kc][0] = *(const uint32_t*)&hlB[(size_t)prow0 * DD + kc * 16 + ac];
        Alo[kc][1] = *(const uint32_t*)&hlB[(size_t)prow1 * DD + kc * 16 + ac];
        Alo[kc][2] = *(const uint32_t*)&hlB[(size_t)prow0 * DD + kc * 16 + 8 + ac];
        Alo[kc][3] = *(const uint32_t*)&hlB[(size_t)prow1 * DD + kc * 16 + 8 + ac];
    }
    const float rp0 = rnB[prow0];
    const float rp1 = rnB[prow1];

    float O[16][4];
    #pragma unroll
    for (int i = 0; i < 16; i++)
        #pragma unroll
        for (int j = 0; j < 4; j++) O[i][j] = 0.0f;

    const uint32_t off1 = (uint32_t)((lane & 7) * (HQS * 2) + (lane >> 3) * 16);
    const uint32_t off2 = (uint32_t)((lane & 15) * (HQS * 2) + (lane >> 4) * 16);

    // ---- staging: 16B per thread x 8 passes per (hi|lo) via cp.async ----
    auto stage = [&](int qb, int buf) {
        const uint32_t dhi = sbase + buf * 2 * TILE_B;
        const uint32_t dlo = dhi + TILE_B;
        #pragma unroll
        for (int i = 0; i < 8; i++) {
            const int idx = i * 128 + t;
            const int r = idx >> 4, c = idx & 15;
            const uint32_t doff = (uint32_t)(r * (HQS * 2) + c * 16);
            CP_ASYNC16(dhi + doff, (const char*)&hhB[(size_t)(qb + r) * DD + c * 8]);
            CP_ASYNC16(dlo + doff, (const char*)&hlB[(size_t)(qb + r) * DD + c * 8]);
        }
    };

    stage(0, 0);
    CP_COMMIT();

    for (int it = 0; it < NN / QT; it++) {
        const int qb = it * QT;
        const int cur = it & 1;
        const uint32_t sHi = sbase + cur * 2 * TILE_B;
        const uint32_t sLo = sHi + TILE_B;

        __syncthreads();                       // prev compute done with buf[cur^1]
        if (qb + QT < NN) {
            stage(qb + QT, cur ^ 1);
            CP_COMMIT();
            CP_WAIT(1);
        } else {
            CP_WAIT(0);
        }
        __syncthreads();                       // buf[cur] visible to all

        // ---- GEMM1: S = AhiBhi + AloBhi + AhiBlo ----
        float S[8][4];
        #pragma unroll
        for (int i = 0; i < 8; i++)
            #pragma unroll
            for (int j = 0; j < 4; j++) S[i][j] = 0.0f;

        #pragma unroll
        for (int kp = 0; kp < 4; kp++) {
            #pragma unroll
            for (int nc = 0; nc < 8; nc++) {
                const uint32_t base = (uint32_t)(nc * 8 * (HQS * 2) + kp * 64);
                uint32_t bh[4], bl[4];
                ldsm4(bh, sHi + base + off1);
                mma_bf16(S[nc], Ahi[2 * kp],     bh + 0);
                mma_bf16(S[nc], Ahi[2 * kp + 1], bh + 2);
                mma_bf16(S[nc], Alo[2 * kp],     bh + 0);
                mma_bf16(S[nc], Alo[2 * kp + 1], bh + 2);
                ldsm4(bl, sLo + base + off1);
                mma_bf16(S[nc], Ahi[2 * kp],     bl + 0);
                mma_bf16(S[nc], Ahi[2 * kp + 1], bl + 2);
            }
        }

        // ---- mask: S *= rp * rq * ew ----
        #pragma unroll
        for (int nc = 0; nc < 8; nc++) {
            const int qcol = qb + nc * 8 + ac;
            const float2 e0 = *(const float2*)&ewB[(size_t)prow0 * NN + qcol];
            const float2 e1 = *(const float2*)&ewB[(size_t)prow1 * NN + qcol];
            const float2 rq = *(const float2*)&rnB[qcol];
            S[nc][0] *= rp0 * rq.x * e0.x;
            S[nc][1] *= rp0 * rq.y * e0.y;
            S[nc][2] *= rp1 * rq.x * e1.x;
            S[nc][3] *= rp1 * rq.y * e1.y;
        }

        // ---- split S -> P fragments ----
        uint32_t Phi[4][4], Plo[4][4];
        #pragma unroll
        for (int kc = 0; kc < 4; kc++) {
            split2(S[2 * kc][0],     S[2 * kc][1],     Phi[kc][0], Plo[kc][0]);
            split2(S[2 * kc][2],     S[2 * kc][3],     Phi[kc][1], Plo[kc][1]);
            split2(S[2 * kc + 1][0], S[2 * kc + 1][1], Phi[kc][2], Plo[kc][2]);
            split2(S[2 * kc + 1][2], S[2 * kc + 1][3], Phi[kc][3], Plo[kc][3]);
        }

        // ---- GEMM2: O += PhiBhi + PloBhi + PhiBlo (B via ldsm.trans) ----
        #pragma unroll
        for (int kc = 0; kc < 4; kc++) {
            #pragma unroll
            for (int np = 0; np < 8; np++) {
                const uint32_t base = (uint32_t)(kc * 16 * (HQS * 2) + np * 32);
                uint32_t bh[4], bl[4];
                ldsm4t(bh, sHi + base + off2);
                mma_bf16(O[2 * np],     Phi[kc], bh + 0);
                mma_bf16(O[2 * np + 1], Phi[kc], bh + 2);
                mma_bf16(O[2 * np],     Plo[kc], bh + 0);
                mma_bf16(O[2 * np + 1], Plo[kc], bh + 2);
                ldsm4t(bl, sLo + base + off2);
                mma_bf16(O[2 * np],     Phi[kc], bl + 0);
                mma_bf16(O[2 * np + 1], Phi[kc], bl + 2);
            }
        }
    }

    // ---- epilogue ----
    float* outB = out + (size_t)b * NN * DD;
    #pragma unroll
    for (int nc = 0; nc < 16; nc++) {
        float v0 = O[nc][0], v1 = O[nc][1], v2 = O[nc][2], v3 = O[nc][3];
        if (do_relu) {
            v0 = fmaxf(v0, 0.0f); v1 = fmaxf(v1, 0.0f);
            v2 = fmaxf(v2, 0.0f); v3 = fmaxf(v3, 0.0f);
        }
        *(float2*)&outB[(size_t)prow0 * DD + nc * 8 + ac] = make_float2(v0, v1);
        *(float2*)&outB[(size_t)prow1 * DD + nc * 8 + ac] = make_float2(v2, v3);
    }
}

// ---------------------------------------------------------------------------
extern "C" void kernel_launch(void* const* d_in, const int* in_sizes, int n_in,
                              void* d_out, int out_size)
{
    const float* x  = (const float*)d_in[0];
    const float* ew = (const float*)d_in[1];
    const float* W[3]  = {(const float*)d_in[2], (const float*)d_in[4], (const float*)d_in[6]};
    const float* bb[3] = {(const float*)d_in[3], (const float*)d_in[5], (const float*)d_in[7]};
    float* out = (float*)d_out;

    float *buf, *rn;
    __nv_bfloat16 *hhi, *hlo;
    cudaGetSymbolAddress((void**)&buf, g_buf);
    cudaGetSymbolAddress((void**)&rn, g_rn);
    cudaGetSymbolAddress((void**)&hhi, g_hhi);
    cudaGetSymbolAddress((void**)&hlo, g_hlo);

    cudaFuncSetAttribute(linear_norm_kernel,
                         cudaFuncAttributeMaxDynamicSharedMemorySize, SMEM_LIN);
    cudaFuncSetAttribute(fused_mma_kernel,
                         cudaFuncAttributeMaxDynamicSharedMemorySize, SMEM_FUSED);

    const dim3 gl(ROWS_TOT / 64);
    const dim3 gf(NN / 64, NB);

    const float* cur = x;
    for (int l = 0; l < 3; l++) {
        linear_norm_kernel<<<gl, 256, SMEM_LIN>>>(cur, W[l], bb[l], hhi, hlo, rn);
        float* dst = (l == 2) ? out : buf;
        fused_mma_kernel<<<gf, 128, SMEM_FUSED>>>(hhi, hlo, rn, ew, dst, (l < 2) ? 1 : 0);
        cur = buf;
    }
}

// round 5
// speedup vs baseline: 1.0839x; 1.0839x over previous
#include <cuda_runtime.h>
#include <cuda_bf16.h>
#include <cstdint>
#include <math.h>

#define NB 8
#define NN 2048
#define DD 128
#define ROWS_TOT (NB * NN)

__device__ float g_buf[ROWS_TOT * DD];
__device__ __nv_bfloat16 g_hhi[ROWS_TOT * DD];
__device__ __nv_bfloat16 g_hlo[ROWS_TOT * DD];
__device__ float g_rn[ROWS_TOT];

// ---------------------------------------------------------------------------
__device__ __forceinline__ uint32_t smem_u32(const void* p) {
    uint32_t a;
    asm("{ .reg .u64 t; cvta.to.shared.u64 t, %1; cvt.u32.u64 %0, t; }" : "=r"(a) : "l"(p));
    return a;
}
__device__ __forceinline__ void mma_bf16(float* d, const uint32_t* a, const uint32_t* b) {
    asm volatile(
        "mma.sync.aligned.m16n8k16.row.col.f32.bf16.bf16.f32 "
        "{%0,%1,%2,%3}, {%4,%5,%6,%7}, {%8,%9}, {%0,%1,%2,%3};"
        : "+f"(d[0]), "+f"(d[1]), "+f"(d[2]), "+f"(d[3])
        : "r"(a[0]), "r"(a[1]), "r"(a[2]), "r"(a[3]), "r"(b[0]), "r"(b[1]));
}
__device__ __forceinline__ void ldsm4(uint32_t* r, uint32_t addr) {
    asm volatile("ldmatrix.sync.aligned.m8n8.x4.shared.b16 {%0,%1,%2,%3}, [%4];"
                 : "=r"(r[0]), "=r"(r[1]), "=r"(r[2]), "=r"(r[3]) : "r"(addr));
}
__device__ __forceinline__ void ldsm4t(uint32_t* r, uint32_t addr) {
    asm volatile("ldmatrix.sync.aligned.m8n8.x4.trans.shared.b16 {%0,%1,%2,%3}, [%4];"
                 : "=r"(r[0]), "=r"(r[1]), "=r"(r[2]), "=r"(r[3]) : "r"(addr));
}
__device__ __forceinline__ uint32_t packbf(float a, float b) {
    const uint16_t la = __bfloat16_as_ushort(__float2bfloat16(a));
    const uint16_t lb = __bfloat16_as_ushort(__float2bfloat16(b));
    return ((uint32_t)lb << 16) | la;
}
__device__ __forceinline__ void split2(float v0, float v1, uint32_t& hi, uint32_t& lo) {
    const __nv_bfloat16 h0 = __float2bfloat16(v0);
    const __nv_bfloat16 h1 = __float2bfloat16(v1);
    const float r0 = v0 - __bfloat162float(h0);
    const float r1 = v1 - __bfloat162float(h1);
    hi = ((uint32_t)__bfloat16_as_ushort(h1) << 16) | __bfloat16_as_ushort(h0);
    lo = packbf(r0, r1);
}
#define CP_ASYNC16(dst, src) \
    asm volatile("cp.async.cg.shared.global [%0], [%1], 16;" :: "r"(dst), "l"(src))
#define CP_COMMIT() asm volatile("cp.async.commit_group;" ::: "memory")
#define CP_WAIT(n)  asm volatile("cp.async.wait_group %0;" :: "n"(n) : "memory")

// ---------------------------------------------------------------------------
// Linear + bias + split + reciprocal norm (unchanged, proven)
// ---------------------------------------------------------------------------
#define SMEM_LIN ((64 * 132 + 128 * 132) * 4)

__global__ __launch_bounds__(256, 2) void linear_norm_kernel(
    const float* __restrict__ in, const float* __restrict__ W, const float* __restrict__ bias,
    __nv_bfloat16* __restrict__ hhi, __nv_bfloat16* __restrict__ hlo, float* __restrict__ rn)
{
    extern __shared__ float sm[];
    float* sx = sm;
    float* sw = sm + 64 * 132;

    const int t = threadIdx.x;
    const int rowbase = blockIdx.x * 64;
    const int f4 = (t & 31) * 4;
    const int r0 = t >> 5;

    #pragma unroll
    for (int r = r0; r < 64; r += 8)
        *(float4*)&sx[r * 132 + f4] = *(const float4*)&in[(size_t)(rowbase + r) * DD + f4];
    #pragma unroll
    for (int r = r0; r < 128; r += 8)
        *(float4*)&sw[r * 132 + f4] = *(const float4*)&W[(size_t)r * DD + f4];
    __syncthreads();

    const int tx = t & 15;
    const int ty = t >> 4;

    float acc[4][8];
    #pragma unroll
    for (int i = 0; i < 4; i++)
        #pragma unroll
        for (int j = 0; j < 8; j++) acc[i][j] = 0.0f;

    #pragma unroll 4
    for (int k = 0; k < DD; k++) {
        float a[4], w[8];
        #pragma unroll
        for (int i = 0; i < 4; i++) a[i] = sx[(ty * 4 + i) * 132 + k];
        #pragma unroll
        for (int j = 0; j < 8; j++) w[j] = sw[k * 132 + tx + 16 * j];
        #pragma unroll
        for (int i = 0; i < 4; i++)
            #pragma unroll
            for (int j = 0; j < 8; j++)
                acc[i][j] = fmaf(a[i], w[j], acc[i][j]);
    }

    float bv[8];
    #pragma unroll
    for (int j = 0; j < 8; j++) bv[j] = bias[tx + 16 * j];

    #pragma unroll
    for (int i = 0; i < 4; i++) {
        float ss = 0.0f;
        #pragma unroll
        for (int j = 0; j < 8; j++) {
            acc[i][j] += bv[j];
            ss = fmaf(acc[i][j], acc[i][j], ss);
        }
        #pragma unroll
        for (int off = 8; off > 0; off >>= 1)
            ss += __shfl_xor_sync(0xffffffffu, ss, off, 16);
        if (tx == 0)
            rn[rowbase + ty * 4 + i] = 1.0f / fmaxf(sqrtf(ss), 1e-12f);
    }

    #pragma unroll
    for (int i = 0; i < 4; i++)
        #pragma unroll
        for (int j = 0; j < 8; j++) {
            const float v = acc[i][j];
            const __nv_bfloat16 h = __float2bfloat16(v);
            const __nv_bfloat16 l = __float2bfloat16(v - __bfloat162float(h));
            const size_t idx = (size_t)(rowbase + ty * 4 + i) * DD + tx + 16 * j;
            hhi[idx] = h;
            hlo[idx] = l;
        }
}

// ---------------------------------------------------------------------------
// Fused flash aggregation. 256 threads = 8 warps, 128 p-rows/CTA, grid 128.
// Double-buffered cp.async staging of Hq(hi/lo), ew block, and rq.
// ---------------------------------------------------------------------------
#define QT 64
#define HQS 136                         // bf16 elems per smem row (272 B)
#define TILE_B (QT * HQS * 2)           // 17408 B per (hi|lo) Hq tile
#define EWS 72                          // ew smem row stride (floats) = 288 B (16B-aligned)
#define EW_B (128 * EWS * 4)            // 36864 B per ew stage
#define RQ_B 256                        // 64 floats
#define STAGE_EW_B (EW_B + RQ_B)
#define OFF_EW (4 * TILE_B)             // after 2 stages x (hi+lo)
#define SMEM_FUSED (OFF_EW + 2 * STAGE_EW_B)

__global__ __launch_bounds__(256, 1) void fused_mma_kernel(
    const __nv_bfloat16* __restrict__ hhi, const __nv_bfloat16* __restrict__ hlo,
    const float* __restrict__ rn, const float* __restrict__ ew,
    float* __restrict__ out, int do_relu)
{
    extern __shared__ char smem[];
    const uint32_t sbase = smem_u32(smem);

    const int t = threadIdx.x;
    const int w = t >> 5;
    const int lane = t & 31;
    const int quad = lane & 3;
    const int gr = lane >> 2;
    const int b = blockIdx.y;
    const int pbase = blockIdx.x * 128;

    const __nv_bfloat16* hhB = hhi + (size_t)b * NN * DD;
    const __nv_bfloat16* hlB = hlo + (size_t)b * NN * DD;
    const float* rnB = rn + (size_t)b * NN;
    const float* ewB = ew + (size_t)b * NN * NN;

    const int prow0 = pbase + w * 16 + gr;
    const int prow1 = prow0 + 8;
    const int ac = quad * 2;

    // ---- A fragments (Hp hi/lo) resident in registers ----
    uint32_t Ahi[8][4], Alo[8][4];
    #pragma unroll
    for (int kc = 0; kc < 8; kc++) {
        Ahi[kc][0] = *(const uint32_t*)&hhB[(size_t)prow0 * DD + kc * 16 + ac];
        Ahi[kc][1] = *(const uint32_t*)&hhB[(size_t)prow1 * DD + kc * 16 + ac];
        Ahi[kc][2] = *(const uint32_t*)&hhB[(size_t)prow0 * DD + kc * 16 + 8 + ac];
        Ahi[kc][3] = *(const uint32_t*)&hhB[(size_t)prow1 * DD + kc * 16 + 8 + ac];
        Alo[kc][0] = *(const uint32_t*)&hlB[(size_t)prow0 * DD + kc * 16 + ac];
        Alo[kc][1] = *(const uint32_t*)&hlB[(size_t)prow1 * DD + kc * 16 + ac];
        Alo[kc][2] = *(const uint32_t*)&hlB[(size_t)prow0 * DD + kc * 16 + 8 + ac];
        Alo[kc][3] = *(const uint32_t*)&hlB[(size_t)prow1 * DD + kc * 16 + 8 + ac];
    }
    const float rp0 = rnB[prow0];
    const float rp1 = rnB[prow1];

    float O[16][4];
    #pragma unroll
    for (int i = 0; i < 16; i++)
        #pragma unroll
        for (int j = 0; j < 4; j++) O[i][j] = 0.0f;

    const uint32_t off1 = (uint32_t)((lane & 7) * (HQS * 2) + (lane >> 3) * 16);
    const uint32_t off2 = (uint32_t)((lane & 15) * (HQS * 2) + (lane >> 4) * 16);

    // ---- staging lambdas ----
    auto stage = [&](int qb, int buf) {
        // Hq tiles: 64 rows x 16 chunks (hi+lo) -> 4 chunks/thread each
        const uint32_t dhi = sbase + buf * 2 * TILE_B;
        const uint32_t dlo = dhi + TILE_B;
        #pragma unroll
        for (int i = 0; i < 4; i++) {
            const int idx = i * 256 + t;
            const int r = idx >> 4, c = idx & 15;
            const uint32_t doff = (uint32_t)(r * (HQS * 2) + c * 16);
            CP_ASYNC16(dhi + doff, (const char*)&hhB[(size_t)(qb + r) * DD + c * 8]);
            CP_ASYNC16(dlo + doff, (const char*)&hlB[(size_t)(qb + r) * DD + c * 8]);
        }
        // ew block: 128 rows x 16 chunks -> 8 chunks/thread
        const uint32_t dew = sbase + OFF_EW + buf * STAGE_EW_B;
        #pragma unroll
        for (int i = 0; i < 8; i++) {
            const int idx = i * 256 + t;
            const int r = idx >> 4, c = idx & 15;
            CP_ASYNC16(dew + (uint32_t)(r * (EWS * 4) + c * 16),
                       (const char*)&ewB[(size_t)(pbase + r) * NN + qb + c * 4]);
        }
        // rq: 64 floats = 16 chunks
        if (t < 16)
            CP_ASYNC16(dew + (uint32_t)(EW_B + t * 16), (const char*)&rnB[qb + t * 4]);
    };

    stage(0, 0);
    CP_COMMIT();

    for (int it = 0; it < NN / QT; it++) {
        const int qb = it * QT;
        const int cur = it & 1;
        const uint32_t sHi = sbase + cur * 2 * TILE_B;
        const uint32_t sLo = sHi + TILE_B;
        const float* sewf = (const float*)(smem + OFF_EW + cur * STAGE_EW_B);
        const float* srqf = (const float*)(smem + OFF_EW + cur * STAGE_EW_B + EW_B);

        if (qb + QT < NN) {
            stage(qb + QT, cur ^ 1);   // prefetch into the buffer freed last iter
            CP_COMMIT();
            CP_WAIT(1);
        } else {
            CP_WAIT(0);
        }
        __syncthreads();               // buf[cur] (incl. ew/rq) visible to all

        // ---- GEMM1: S = AhiBhi + AloBhi + AhiBlo ----
        float S[8][4];
        #pragma unroll
        for (int i = 0; i < 8; i++)
            #pragma unroll
            for (int j = 0; j < 4; j++) S[i][j] = 0.0f;

        #pragma unroll
        for (int kp = 0; kp < 4; kp++) {
            #pragma unroll
            for (int nc = 0; nc < 8; nc++) {
                const uint32_t base = (uint32_t)(nc * 8 * (HQS * 2) + kp * 64);
                uint32_t bh[4], bl[4];
                ldsm4(bh, sHi + base + off1);
                mma_bf16(S[nc], Ahi[2 * kp],     bh + 0);
                mma_bf16(S[nc], Ahi[2 * kp + 1], bh + 2);
                mma_bf16(S[nc], Alo[2 * kp],     bh + 0);
                mma_bf16(S[nc], Alo[2 * kp + 1], bh + 2);
                ldsm4(bl, sLo + base + off1);
                mma_bf16(S[nc], Ahi[2 * kp],     bl + 0);
                mma_bf16(S[nc], Ahi[2 * kp + 1], bl + 2);
            }
        }

        // ---- mask from smem: S *= rp * rq * ew ----
        const int lr0 = w * 16 + gr;
        #pragma unroll
        for (int nc = 0; nc < 8; nc++) {
            const int col = nc * 8 + ac;
            const float2 e0 = *(const float2*)&sewf[lr0 * EWS + col];
            const float2 e1 = *(const float2*)&sewf[(lr0 + 8) * EWS + col];
            const float2 rq = *(const float2*)&srqf[col];
            S[nc][0] *= rp0 * rq.x * e0.x;
            S[nc][1] *= rp0 * rq.y * e0.y;
            S[nc][2] *= rp1 * rq.x * e1.x;
            S[nc][3] *= rp1 * rq.y * e1.y;
        }

        // ---- split S -> P fragments ----
        uint32_t Phi[4][4], Plo[4][4];
        #pragma unroll
        for (int kc = 0; kc < 4; kc++) {
            split2(S[2 * kc][0],     S[2 * kc][1],     Phi[kc][0], Plo[kc][0]);
            split2(S[2 * kc][2],     S[2 * kc][3],     Phi[kc][1], Plo[kc][1]);
            split2(S[2 * kc + 1][0], S[2 * kc + 1][1], Phi[kc][2], Plo[kc][2]);
            split2(S[2 * kc + 1][2], S[2 * kc + 1][3], Phi[kc][3], Plo[kc][3]);
        }

        // ---- GEMM2: O += PhiBhi + PloBhi + PhiBlo (B via ldsm.trans) ----
        #pragma unroll
        for (int kc = 0; kc < 4; kc++) {
            #pragma unroll
            for (int np = 0; np < 8; np++) {
                const uint32_t base = (uint32_t)(kc * 16 * (HQS * 2) + np * 32);
                uint32_t bh[4], bl[4];
                ldsm4t(bh, sHi + base + off2);
                mma_bf16(O[2 * np],     Phi[kc], bh + 0);
                mma_bf16(O[2 * np + 1], Phi[kc], bh + 2);
                mma_bf16(O[2 * np],     Plo[kc], bh + 0);
                mma_bf16(O[2 * np + 1], Plo[kc], bh + 2);
                ldsm4t(bl, sLo + base + off2);
                mma_bf16(O[2 * np],     Phi[kc], bl + 0);
                mma_bf16(O[2 * np + 1], Phi[kc], bl + 2);
            }
        }
        __syncthreads();               // compute done with buf[cur] before restage
    }

    // ---- epilogue ----
    float* outB = out + (size_t)b * NN * DD;
    #pragma unroll
    for (int nc = 0; nc < 16; nc++) {
        float v0 = O[nc][0], v1 = O[nc][1], v2 = O[nc][2], v3 = O[nc][3];
        if (do_relu) {
            v0 = fmaxf(v0, 0.0f); v1 = fmaxf(v1, 0.0f);
            v2 = fmaxf(v2, 0.0f); v3 = fmaxf(v3, 0.0f);
        }
        *(float2*)&outB[(size_t)prow0 * DD + nc * 8 + ac] = make_float2(v0, v1);
        *(float2*)&outB[(size_t)prow1 * DD + nc * 8 + ac] = make_float2(v2, v3);
    }
}

// ---------------------------------------------------------------------------
extern "C" void kernel_launch(void* const* d_in, const int* in_sizes, int n_in,
                              void* d_out, int out_size)
{
    const float* x  = (const float*)d_in[0];
    const float* ew = (const float*)d_in[1];
    const float* W[3]  = {(const float*)d_in[2], (const float*)d_in[4], (const float*)d_in[6]};
    const float* bb[3] = {(const float*)d_in[3], (const float*)d_in[5], (const float*)d_in[7]};
    float* out = (float*)d_out;

    float *buf, *rn;
    __nv_bfloat16 *hhi, *hlo;
    cudaGetSymbolAddress((void**)&buf, g_buf);
    cudaGetSymbolAddress((void**)&rn, g_rn);
    cudaGetSymbolAddress((void**)&hhi, g_hhi);
    cudaGetSymbolAddress((void**)&hlo, g_hlo);

    cudaFuncSetAttribute(linear_norm_kernel,
                         cudaFuncAttributeMaxDynamicSharedMemorySize, SMEM_LIN);
    cudaFuncSetAttribute(fused_mma_kernel,
                         cudaFuncAttributeMaxDynamicSharedMemorySize, SMEM_FUSED);

    const dim3 gl(ROWS_TOT / 64);
    const dim3 gf(NN / 128, NB);

    const float* cur = x;
    for (int l = 0; l < 3; l++) {
        linear_norm_kernel<<<gl, 256, SMEM_LIN>>>(cur, W[l], bb[l], hhi, hlo, rn);
        float* dst = (l == 2) ? out : buf;
        fused_mma_kernel<<<gf, 256, SMEM_FUSED>>>(hhi, hlo, rn, ew, dst, (l < 2) ? 1 : 0);
        cur = buf;
    }
}